// round 15
// baseline (speedup 1.0000x reference)
#include <cuda_runtime.h>
#include <cstdint>

#define Bx 4
#define Sx 2048
#define Dx 1024
#define Hx 16
#define DKx 64
#define SW 36      // gemm smem stride (floats) — unchanged, proven
#define AW 72      // attn smem stride (uint32): 72 mod 32 == 8 -> conflict-free LDS.64 pairs

__device__ uint32_t g_Q[(size_t)Bx*Hx*Sx*DKx];    // tf32 bits
__device__ uint32_t g_K[(size_t)Bx*Hx*Sx*DKx];    // tf32 bits
__device__ uint32_t g_Vt[(size_t)Bx*Hx*Sx*DKx];   // tf32 bits, [B,H,DK,S]
__device__ float    g_C[(size_t)Bx*Hx*Sx*DKx];
__device__ unsigned g_mb[(size_t)Bx*Sx*(Sx/32)];

__device__ __forceinline__ uint32_t f2tf(float x) {
    uint32_t r; asm("cvt.rna.tf32.f32 %0, %1;" : "=r"(r) : "f"(x)); return r;
}
__device__ __forceinline__ float ex2(float x) {
    float r; asm("ex2.approx.f32 %0, %1;" : "=f"(r) : "f"(x)); return r;
}
__device__ __forceinline__ void mma8(float* d, const uint32_t* a, const uint32_t* b) {
    asm volatile("mma.sync.aligned.m16n8k8.row.col.f32.tf32.tf32.f32 "
        "{%0,%1,%2,%3}, {%4,%5,%6,%7}, {%8,%9}, {%0,%1,%2,%3};"
        : "+f"(d[0]), "+f"(d[1]), "+f"(d[2]), "+f"(d[3])
        : "r"(a[0]), "r"(a[1]), "r"(a[2]), "r"(a[3]), "r"(b[0]), "r"(b[1]));
}
__device__ __forceinline__ void cp16(void* s, const void* g) {
    uint32_t sa = (uint32_t)__cvta_generic_to_shared(s);
    asm volatile("cp.async.cg.shared.global [%0], [%1], 16;" :: "r"(sa), "l"(g));
}
__device__ __forceinline__ void cp8(void* s, const void* g) {
    uint32_t sa = (uint32_t)__cvta_generic_to_shared(s);
    asm volatile("cp.async.ca.shared.global [%0], [%1], 8;" :: "r"(sa), "l"(g));
}
#define CP_COMMIT() asm volatile("cp.async.commit_group;")
#define CP_WAIT(N)  asm volatile("cp.async.wait_group %0;" :: "n"(N))

// ---------------------------------------------------------------------------
__global__ void pack_mask(const int* __restrict__ mask, unsigned* __restrict__ mb)
{
    size_t i = (size_t)blockIdx.x * blockDim.x + threadIdx.x;
    int v = mask[i] != 0;
    unsigned bits = __ballot_sync(0xffffffffu, v);
    if ((threadIdx.x & 31) == 0) mb[i >> 5] = bits;
}

// ---------------------------------------------------------------------------
// tf32 GEMM body (R7-proven): out = A @ W^T + bias. CTA 128x128, BK=32.
// MODE 0: store tf32 BITS remapped to [B,H,S,DK]
// MODE 1: A gathered from fp32 [B,H,S,DK]; store fp32 [B*S,D]
// MODE 2: store tf32 BITS remapped to [B,H,DK,S]
// ---------------------------------------------------------------------------
template<int MODE>
__device__ __forceinline__
void gemm_body(const float* __restrict__ A, const float* __restrict__ W,
               const float* __restrict__ bias, void* __restrict__ outv,
               float* sm)
{
    float* As = sm;                 // [2][128][SW]
    float* Bs = sm + 2*128*SW;      // [2][128][SW]

    const int tid  = threadIdx.x;
    const int lane = tid & 31;
    const int w    = tid >> 5;
    const int wm   = (w >> 2) * 64;
    const int wn   = (w & 3) * 32;
    const int rbase = blockIdx.x * 128;
    const int cbase = blockIdx.y * 128;
    const int lr = lane >> 2, lc = lane & 3;

    float acc[4][4][4];
    #pragma unroll
    for (int i = 0; i < 4; i++)
        #pragma unroll
        for (int j = 0; j < 4; j++)
            #pragma unroll
            for (int k = 0; k < 4; k++) acc[i][j][k] = 0.f;

    auto load_stage = [&](int st, int k0) {
        #pragma unroll
        for (int i = 0; i < 4; i++) {
            int q = tid + i * 256;
            int row = q >> 3, cq = (q & 7) * 4;
            const float* srcA;
            if (MODE == 1) {
                int gr = rbase + row, k = k0 + cq;
                srcA = A + (((size_t)(gr >> 11) * Hx + (k >> 6)) * Sx + (gr & (Sx-1))) * DKx + (k & 63);
            } else {
                srcA = A + (size_t)(rbase + row) * Dx + k0 + cq;
            }
            cp16(As + ((size_t)st * 128 + row) * SW + cq, srcA);
            cp16(Bs + ((size_t)st * 128 + row) * SW + cq,
                 W + (size_t)(cbase + row) * Dx + k0 + cq);
        }
        CP_COMMIT();
    };

    load_stage(0, 0);
    const int NIT = Dx / 32;
    for (int it = 0; it < NIT; it++) {
        if (it + 1 < NIT) { load_stage((it + 1) & 1, (it + 1) * 32); CP_WAIT(1); }
        else              { CP_WAIT(0); }
        __syncthreads();
        const float* a   = As + (size_t)(it & 1) * 128 * SW;
        const float* bsh = Bs + (size_t)(it & 1) * 128 * SW;
        #pragma unroll
        for (int ks = 0; ks < 4; ks++) {
            const int kk = ks * 8 + lc;
            uint32_t af[4][4], bf[4][2];
            #pragma unroll
            for (int mt = 0; mt < 4; mt++) {
                const float* p = a + (wm + mt * 16 + lr) * SW + kk;
                af[mt][0] = f2tf(p[0]);
                af[mt][1] = f2tf(p[8 * SW]);
                af[mt][2] = f2tf(p[4]);
                af[mt][3] = f2tf(p[8 * SW + 4]);
            }
            #pragma unroll
            for (int nt = 0; nt < 4; nt++) {
                const float* p = bsh + (wn + nt * 8 + lr) * SW + kk;
                bf[nt][0] = f2tf(p[0]);
                bf[nt][1] = f2tf(p[4]);
            }
            #pragma unroll
            for (int mt = 0; mt < 4; mt++)
                #pragma unroll
                for (int nt = 0; nt < 4; nt++)
                    mma8(acc[mt][nt], af[mt], bf[nt]);
        }
        __syncthreads();
    }

    #pragma unroll
    for (int mt = 0; mt < 4; mt++) {
        int row = rbase + wm + mt * 16 + lr;
        #pragma unroll
        for (int nt = 0; nt < 4; nt++) {
            int col = cbase + wn + nt * 8 + 2 * lc;
            float b0 = bias[col], b1 = bias[col + 1];
            float v0 = acc[mt][nt][0] + b0, v1 = acc[mt][nt][1] + b1;
            float v2 = acc[mt][nt][2] + b0, v3 = acc[mt][nt][3] + b1;
            if (MODE == 0) {
                uint32_t* out = (uint32_t*)outv;
                int bb = row >> 11, ss = row & (Sx - 1);
                int hh = col >> 6,  dd = col & 63;
                size_t base = ((size_t)bb * Hx + hh) * Sx;
                *(uint2*)&out[(base + ss) * DKx + dd]     = make_uint2(f2tf(v0), f2tf(v1));
                *(uint2*)&out[(base + ss + 8) * DKx + dd] = make_uint2(f2tf(v2), f2tf(v3));
            } else if (MODE == 1) {
                float* out = (float*)outv;
                *(float2*)&out[(size_t)row * Dx + col]       = make_float2(v0, v1);
                *(float2*)&out[(size_t)(row + 8) * Dx + col] = make_float2(v2, v3);
            } else {
                uint32_t* out = (uint32_t*)outv;
                int bb = row >> 11, ss = row & (Sx - 1);
                int hh = col >> 6,  dd = col & 63;
                size_t base = ((size_t)bb * Hx + hh) * DKx;
                out[(base + dd)     * Sx + ss]     = f2tf(v0);
                out[(base + dd + 1) * Sx + ss]     = f2tf(v1);
                out[(base + dd)     * Sx + ss + 8] = f2tf(v2);
                out[(base + dd + 1) * Sx + ss + 8] = f2tf(v3);
            }
        }
    }
}

__global__ __launch_bounds__(256, 2)
void gemm_qk(const float* __restrict__ A0, const float* __restrict__ W0,
             const float* __restrict__ b0, uint32_t* __restrict__ o0,
             const float* __restrict__ A1, const float* __restrict__ W1,
             const float* __restrict__ b1, uint32_t* __restrict__ o1)
{
    extern __shared__ float sm[];
    if (blockIdx.z == 0) gemm_body<0>(A0, W0, b0, o0, sm);
    else                 gemm_body<0>(A1, W1, b1, o1, sm);
}

template<int MODE>
__global__ __launch_bounds__(256, 2)
void gemm_one(const float* __restrict__ A, const float* __restrict__ W,
              const float* __restrict__ bias, void* __restrict__ out)
{
    extern __shared__ float sm[];
    gemm_body<MODE>(A, W, bias, out, sm);
}

// ---------------------------------------------------------------------------
// Fused flash attention. 128 threads / 4 warps, q-tile 128 (32 rows/warp,
// mt=2), k-tile 64, double-buffered; 2 decoupled CTAs/SM. Doubling rows/warp
// halves the per-CTA K/V fragment redundancy: LDS.64 per HMMA drops from
// 1.125 to 0.625, cutting smem-crossbar demand ~45% (the measured L1=64%
// wall). tf32-bit operands, paired conflict-free LDS.64 (AW=72), PV A-frags
// from QK C-fragments, direct softmax (no max; masked lanes exact zeros).
// ---------------------------------------------------------------------------
__global__ __launch_bounds__(128, 2)
void attn_tf32(float* __restrict__ ctx)
{
    extern __shared__ uint32_t smu[];
    uint32_t* Qs = smu;                          // 128*AW
    uint32_t* Ks = Qs + 128 * AW;                // [2][64*AW]
    uint32_t* Vs = Ks + 2 * 64 * AW;             // [2][64*AW]  ([d][s_local])
    unsigned* MB = (unsigned*)(Vs + 2 * 64 * AW);// [2][256]

    const int tid = threadIdx.x, lane = tid & 31, w = tid >> 5;   // w: 0..3
    const int lr = lane >> 2, lc = lane & 3;
    const int bh = blockIdx.z * Hx + blockIdx.x;
    const int qbase = blockIdx.y * 128;
    const uint32_t* Qg = g_Q  + (size_t)bh * Sx * DKx;
    const uint32_t* Kg = g_K  + (size_t)bh * Sx * DKx;
    const uint32_t* Vg = g_Vt + (size_t)bh * Sx * DKx;   // [d][s]
    const unsigned* mbg = g_mb + ((size_t)blockIdx.z * Sx + qbase) * (Sx / 32);

    #pragma unroll
    for (int i = 0; i < 16; i++) {
        int q = tid + i * 128;
        int row = q >> 4, cq = (q & 15) * 4;
        cp16(Qs + row * AW + cq, Qg + (size_t)(qbase + row) * DKx + cq);
    }

    auto load_kv = [&](int st, int kb) {
        #pragma unroll
        for (int i = 0; i < 8; i++) {
            int q = tid + i * 128;
            int row = q >> 4, cq = (q & 15) * 4;
            cp16(Ks + (st * 64 + row) * AW + cq, Kg + (size_t)(kb + row) * DKx + cq);
            cp16(Vs + (st * 64 + row) * AW + cq, Vg + (size_t)row * Sx + kb + cq);
        }
        // mask: 128 rows x 2 words per stage; thread tid -> row tid
        cp8(MB + st * 256 + tid * 2, mbg + (size_t)tid * (Sx / 32) + (kb >> 5));
        CP_COMMIT();
    };
    load_kv(0, 0);

    float O[2][8][4];
    #pragma unroll
    for (int i = 0; i < 2; i++)
        #pragma unroll
        for (int j = 0; j < 8; j++)
            #pragma unroll
            for (int k = 0; k < 4; k++) O[i][j][k] = 0.f;
    float lrun[4] = {0.f, 0.f, 0.f, 0.f};       // [mt*2+hf]
    const float SC = 0.18033688011112042f;       // 0.125 * log2(e)

    const int NIT = Sx / 64;
    for (int it = 0; it < NIT; it++) {
        if (it + 1 < NIT) { load_kv((it + 1) & 1, (it + 1) * 64); CP_WAIT(1); }
        else              { CP_WAIT(0); }
        __syncthreads();
        const uint32_t* ks_ = Ks + (it & 1) * 64 * AW;
        const uint32_t* vs_ = Vs + (it & 1) * 64 * AW;
        const unsigned* mb_ = MB + (it & 1) * 256;

        // ---- S = Q K^T (paired LDS.64 fragment loads, no cvt) ----
        float S[2][8][4];
        #pragma unroll
        for (int i = 0; i < 2; i++)
            #pragma unroll
            for (int j = 0; j < 8; j++)
                #pragma unroll
                for (int k = 0; k < 4; k++) S[i][j][k] = 0.f;

        #pragma unroll
        for (int ks = 0; ks < 8; ks++) {
            const int kb = ks * 8 + 2 * lc;
            uint32_t qf[2][4], kf[8][2];
            #pragma unroll
            for (int mt = 0; mt < 2; mt++) {
                const uint32_t* p = Qs + (w * 32 + mt * 16 + lr) * AW + kb;
                uint2 p0 = *(const uint2*)p;
                uint2 p1 = *(const uint2*)(p + 8 * AW);
                qf[mt][0] = p0.x; qf[mt][1] = p1.x; qf[mt][2] = p0.y; qf[mt][3] = p1.y;
            }
            #pragma unroll
            for (int nt = 0; nt < 8; nt++) {
                uint2 q0 = *(const uint2*)(ks_ + (nt * 8 + lr) * AW + kb);
                kf[nt][0] = q0.x; kf[nt][1] = q0.y;
            }
            #pragma unroll
            for (int mt = 0; mt < 2; mt++)
                #pragma unroll
                for (int nt = 0; nt < 8; nt++)
                    mma8(S[mt][nt], qf[mt], kf[nt]);
        }

        // ---- mask + direct exp (no max stabilization; sums deferred) ----
        #pragma unroll
        for (int mt = 0; mt < 2; mt++) {
            const int rl = w * 32 + mt * 16 + lr;
            const unsigned m0a = mb_[rl * 2],       m0b = mb_[rl * 2 + 1];
            const unsigned m1a = mb_[(rl + 8) * 2], m1b = mb_[(rl + 8) * 2 + 1];
            #pragma unroll
            for (int nt = 0; nt < 8; nt++) {
                const int sh = (nt * 8 + 2 * lc) & 31;
                const unsigned wa = (nt < 4) ? m0a : m0b;
                const unsigned wb = (nt < 4) ? m1a : m1b;
                float p0 = ((wa >> sh) & 1)       ? ex2(S[mt][nt][0] * SC) : 0.f;
                float p1 = ((wa >> (sh + 1)) & 1) ? ex2(S[mt][nt][1] * SC) : 0.f;
                float p2 = ((wb >> sh) & 1)       ? ex2(S[mt][nt][2] * SC) : 0.f;
                float p3 = ((wb >> (sh + 1)) & 1) ? ex2(S[mt][nt][3] * SC) : 0.f;
                S[mt][nt][0] = p0; S[mt][nt][1] = p1;
                S[mt][nt][2] = p2; S[mt][nt][3] = p3;
                lrun[mt * 2 + 0] += p0 + p1;
                lrun[mt * 2 + 1] += p2 + p3;
            }
        }

        // ---- O += P @ V : A-frag from S's C-fragment registers.
        // k-slot lc := kv 2lc on both sides:
        //   a0=(lr, 2lc)=S[..][0], a1=(lr+8, 2lc)=S[..][2],
        //   a2=(lr, 2lc+1)=S[..][1], a3=S[..][3].
        #pragma unroll
        for (int ks = 0; ks < 8; ks++) {
            const int kb = ks * 8 + 2 * lc;
            uint32_t pf[2][4], vf[8][2];
            #pragma unroll
            for (int mt = 0; mt < 2; mt++) {
                pf[mt][0] = f2tf(S[mt][ks][0]);
                pf[mt][1] = f2tf(S[mt][ks][2]);
                pf[mt][2] = f2tf(S[mt][ks][1]);
                pf[mt][3] = f2tf(S[mt][ks][3]);
            }
            #pragma unroll
            for (int nt = 0; nt < 8; nt++) {
                uint2 q0 = *(const uint2*)(vs_ + (nt * 8 + lr) * AW + kb);
                vf[nt][0] = q0.x; vf[nt][1] = q0.y;
            }
            #pragma unroll
            for (int mt = 0; mt < 2; mt++)
                #pragma unroll
                for (int nt = 0; nt < 8; nt++)
                    mma8(O[mt][nt], pf[mt], vf[nt]);
        }
        __syncthreads();
    }

    // Row-sum reduction once at the end (rows spread over the 4 lc threads).
    #pragma unroll
    for (int mt = 0; mt < 2; mt++)
        #pragma unroll
        for (int hf = 0; hf < 2; hf++) {
            const int idx = mt * 2 + hf;
            lrun[idx] += __shfl_xor_sync(0xffffffffu, lrun[idx], 1);
            lrun[idx] += __shfl_xor_sync(0xffffffffu, lrun[idx], 2);
            const float inv = 1.f / lrun[idx];
            const int row = qbase + w * 32 + mt * 16 + lr + hf * 8;
            float* dst = ctx + ((size_t)bh * Sx + row) * DKx;
            #pragma unroll
            for (int nd = 0; nd < 8; nd++)
                *(float2*)&dst[nd * 8 + 2 * lc] =
                    make_float2(O[mt][nd][2 * hf] * inv, O[mt][nd][2 * hf + 1] * inv);
        }
}

// ---------------------------------------------------------------------------
extern "C" void kernel_launch(void* const* d_in, const int* in_sizes, int n_in,
                              void* d_out, int out_size)
{
    const float* query = (const float*)d_in[0];
    const float* key   = (const float*)d_in[1];
    const float* value = (const float*)d_in[2];
    const int*   mask  = (const int*)d_in[3];
    const float* Wq = (const float*)d_in[4];
    const float* bq = (const float*)d_in[5];
    const float* Wk = (const float*)d_in[6];
    const float* bk = (const float*)d_in[7];
    const float* Wv = (const float*)d_in[8];
    const float* bv = (const float*)d_in[9];
    const float* Wo = (const float*)d_in[10];
    const float* bo = (const float*)d_in[11];
    float* out = (float*)d_out;

    uint32_t *Qb, *Kb, *Vb; float* Cb; unsigned* Mb;
    cudaGetSymbolAddress((void**)&Qb, g_Q);
    cudaGetSymbolAddress((void**)&Kb, g_K);
    cudaGetSymbolAddress((void**)&Vb, g_Vt);
    cudaGetSymbolAddress((void**)&Cb, g_C);
    cudaGetSymbolAddress((void**)&Mb, g_mb);

    const int GSM = 73728;
    const int ASM = (128 + 128 + 128) * AW * 4 + 2048;   // 112640 -> 2 CTAs/SM
    cudaFuncSetAttribute(gemm_qk,     cudaFuncAttributeMaxDynamicSharedMemorySize, GSM);
    cudaFuncSetAttribute(gemm_one<1>, cudaFuncAttributeMaxDynamicSharedMemorySize, GSM);
    cudaFuncSetAttribute(gemm_one<2>, cudaFuncAttributeMaxDynamicSharedMemorySize, GSM);
    cudaFuncSetAttribute(attn_tf32,   cudaFuncAttributeMaxDynamicSharedMemorySize, ASM);

    dim3 blk(256);
    // attn_tf32 stays the 4th launch (ncu captures #4).
    gemm_qk<<<dim3(64, 8, 2), blk, GSM>>>(query, Wq, bq, Qb, key, Wk, bk, Kb); // 1
    gemm_one<2><<<dim3(64, 8), blk, GSM>>>(value, Wv, bv, Vb);                 // 2
    pack_mask<<<65536, 256>>>(mask, Mb);                                       // 3
    attn_tf32<<<dim3(Hx, Sx / 128, Bx), 128, ASM>>>(Cb);                       // 4 <- profiled
    gemm_one<1><<<dim3(64, 8), blk, GSM>>>(Cb, Wo, bo, out);                   // 5
}

// round 17
// speedup vs baseline: 1.0582x; 1.0582x over previous
#include <cuda_runtime.h>
#include <cstdint>

#define Bx 4
#define Sx 2048
#define Dx 1024
#define Hx 16
#define DKx 64
#define SW 36      // gemm smem stride (floats) — unchanged, proven
#define AW 72      // attn smem stride (uint32): 72 mod 32 == 8 -> conflict-free LDS.64 pairs

__device__ uint32_t g_Q[(size_t)Bx*Hx*Sx*DKx];    // tf32 bits
__device__ uint32_t g_K[(size_t)Bx*Hx*Sx*DKx];    // tf32 bits
__device__ uint32_t g_Vt[(size_t)Bx*Hx*Sx*DKx];   // tf32 bits, [B,H,DK,S]
__device__ float    g_C[(size_t)Bx*Hx*Sx*DKx];
__device__ unsigned g_mb[(size_t)Bx*Sx*(Sx/32)];

__device__ __forceinline__ uint32_t f2tf(float x) {
    uint32_t r; asm("cvt.rna.tf32.f32 %0, %1;" : "=r"(r) : "f"(x)); return r;
}
__device__ __forceinline__ void mma8(float* d, const uint32_t* a, const uint32_t* b) {
    asm volatile("mma.sync.aligned.m16n8k8.row.col.f32.tf32.tf32.f32 "
        "{%0,%1,%2,%3}, {%4,%5,%6,%7}, {%8,%9}, {%0,%1,%2,%3};"
        : "+f"(d[0]), "+f"(d[1]), "+f"(d[2]), "+f"(d[3])
        : "r"(a[0]), "r"(a[1]), "r"(a[2]), "r"(a[3]), "r"(b[0]), "r"(b[1]));
}
__device__ __forceinline__ void cp16(void* s, const void* g) {
    uint32_t sa = (uint32_t)__cvta_generic_to_shared(s);
    asm volatile("cp.async.cg.shared.global [%0], [%1], 16;" :: "r"(sa), "l"(g));
}
__device__ __forceinline__ void cp4(void* s, const void* g) {
    uint32_t sa = (uint32_t)__cvta_generic_to_shared(s);
    asm volatile("cp.async.ca.shared.global [%0], [%1], 4;" :: "r"(sa), "l"(g));
}
#define CP_COMMIT() asm volatile("cp.async.commit_group;")
#define CP_WAIT(N)  asm volatile("cp.async.wait_group %0;" :: "n"(N))

// ---------------------------------------------------------------------------
__global__ void pack_mask(const int* __restrict__ mask, unsigned* __restrict__ mb)
{
    size_t i = (size_t)blockIdx.x * blockDim.x + threadIdx.x;
    int v = mask[i] != 0;
    unsigned bits = __ballot_sync(0xffffffffu, v);
    if ((threadIdx.x & 31) == 0) mb[i >> 5] = bits;
}

// ---------------------------------------------------------------------------
// tf32 GEMM body (R7-proven): out = A @ W^T + bias. CTA 128x128, BK=32.
// MODE 0: store tf32 BITS remapped to [B,H,S,DK]
// MODE 1: A gathered from fp32 [B,H,S,DK]; store fp32 [B*S,D]
// MODE 2: store tf32 BITS remapped to [B,H,DK,S]
// ---------------------------------------------------------------------------
template<int MODE>
__device__ __forceinline__
void gemm_body(const float* __restrict__ A, const float* __restrict__ W,
               const float* __restrict__ bias, void* __restrict__ outv,
               float* sm)
{
    float* As = sm;                 // [2][128][SW]
    float* Bs = sm + 2*128*SW;      // [2][128][SW]

    const int tid  = threadIdx.x;
    const int lane = tid & 31;
    const int w    = tid >> 5;
    const int wm   = (w >> 2) * 64;
    const int wn   = (w & 3) * 32;
    const int rbase = blockIdx.x * 128;
    const int cbase = blockIdx.y * 128;
    const int lr = lane >> 2, lc = lane & 3;

    float acc[4][4][4];
    #pragma unroll
    for (int i = 0; i < 4; i++)
        #pragma unroll
        for (int j = 0; j < 4; j++)
            #pragma unroll
            for (int k = 0; k < 4; k++) acc[i][j][k] = 0.f;

    auto load_stage = [&](int st, int k0) {
        #pragma unroll
        for (int i = 0; i < 4; i++) {
            int q = tid + i * 256;
            int row = q >> 3, cq = (q & 7) * 4;
            const float* srcA;
            if (MODE == 1) {
                int gr = rbase + row, k = k0 + cq;
                srcA = A + (((size_t)(gr >> 11) * Hx + (k >> 6)) * Sx + (gr & (Sx-1))) * DKx + (k & 63);
            } else {
                srcA = A + (size_t)(rbase + row) * Dx + k0 + cq;
            }
            cp16(As + ((size_t)st * 128 + row) * SW + cq, srcA);
            cp16(Bs + ((size_t)st * 128 + row) * SW + cq,
                 W + (size_t)(cbase + row) * Dx + k0 + cq);
        }
        CP_COMMIT();
    };

    load_stage(0, 0);
    const int NIT = Dx / 32;
    for (int it = 0; it < NIT; it++) {
        if (it + 1 < NIT) { load_stage((it + 1) & 1, (it + 1) * 32); CP_WAIT(1); }
        else              { CP_WAIT(0); }
        __syncthreads();
        const float* a   = As + (size_t)(it & 1) * 128 * SW;
        const float* bsh = Bs + (size_t)(it & 1) * 128 * SW;
        #pragma unroll
        for (int ks = 0; ks < 4; ks++) {
            const int kk = ks * 8 + lc;
            uint32_t af[4][4], bf[4][2];
            #pragma unroll
            for (int mt = 0; mt < 4; mt++) {
                const float* p = a + (wm + mt * 16 + lr) * SW + kk;
                af[mt][0] = f2tf(p[0]);
                af[mt][1] = f2tf(p[8 * SW]);
                af[mt][2] = f2tf(p[4]);
                af[mt][3] = f2tf(p[8 * SW + 4]);
            }
            #pragma unroll
            for (int nt = 0; nt < 4; nt++) {
                const float* p = bsh + (wn + nt * 8 + lr) * SW + kk;
                bf[nt][0] = f2tf(p[0]);
                bf[nt][1] = f2tf(p[4]);
            }
            #pragma unroll
            for (int mt = 0; mt < 4; mt++)
                #pragma unroll
                for (int nt = 0; nt < 4; nt++)
                    mma8(acc[mt][nt], af[mt], bf[nt]);
        }
        __syncthreads();
    }

    #pragma unroll
    for (int mt = 0; mt < 4; mt++) {
        int row = rbase + wm + mt * 16 + lr;
        #pragma unroll
        for (int nt = 0; nt < 4; nt++) {
            int col = cbase + wn + nt * 8 + 2 * lc;
            float b0 = bias[col], b1 = bias[col + 1];
            float v0 = acc[mt][nt][0] + b0, v1 = acc[mt][nt][1] + b1;
            float v2 = acc[mt][nt][2] + b0, v3 = acc[mt][nt][3] + b1;
            if (MODE == 0) {
                uint32_t* out = (uint32_t*)outv;
                int bb = row >> 11, ss = row & (Sx - 1);
                int hh = col >> 6,  dd = col & 63;
                size_t base = ((size_t)bb * Hx + hh) * Sx;
                *(uint2*)&out[(base + ss) * DKx + dd]     = make_uint2(f2tf(v0), f2tf(v1));
                *(uint2*)&out[(base + ss + 8) * DKx + dd] = make_uint2(f2tf(v2), f2tf(v3));
            } else if (MODE == 1) {
                float* out = (float*)outv;
                *(float2*)&out[(size_t)row * Dx + col]       = make_float2(v0, v1);
                *(float2*)&out[(size_t)(row + 8) * Dx + col] = make_float2(v2, v3);
            } else {
                uint32_t* out = (uint32_t*)outv;
                int bb = row >> 11, ss = row & (Sx - 1);
                int hh = col >> 6,  dd = col & 63;
                size_t base = ((size_t)bb * Hx + hh) * DKx;
                out[(base + dd)     * Sx + ss]     = f2tf(v0);
                out[(base + dd + 1) * Sx + ss]     = f2tf(v1);
                out[(base + dd)     * Sx + ss + 8] = f2tf(v2);
                out[(base + dd + 1) * Sx + ss + 8] = f2tf(v3);
            }
        }
    }
}

// Merged Q/K/V projection: blockIdx.z selects operand set (z=2 is V with
// transposed store). 1536 CTAs -> tails of Q/K fill with V work.
__global__ __launch_bounds__(256, 2)
void gemm_qkv(const float* __restrict__ Aq, const float* __restrict__ Wq,
              const float* __restrict__ bq, uint32_t* __restrict__ oq,
              const float* __restrict__ Ak, const float* __restrict__ Wk,
              const float* __restrict__ bk, uint32_t* __restrict__ ok,
              const float* __restrict__ Av, const float* __restrict__ Wv,
              const float* __restrict__ bv, uint32_t* __restrict__ ov)
{
    extern __shared__ float sm[];
    if (blockIdx.z == 0)      gemm_body<0>(Aq, Wq, bq, oq, sm);
    else if (blockIdx.z == 1) gemm_body<0>(Ak, Wk, bk, ok, sm);
    else                      gemm_body<2>(Av, Wv, bv, ov, sm);
}

template<int MODE>
__global__ __launch_bounds__(256, 2)
void gemm_one(const float* __restrict__ A, const float* __restrict__ W,
              const float* __restrict__ bias, void* __restrict__ out)
{
    extern __shared__ float sm[];
    gemm_body<MODE>(A, W, bias, out, sm);
}

// ---------------------------------------------------------------------------
// Fused flash attention — R12-proven config, verbatim (440us measured).
// 256 threads / 8 warps, q-tile 128 (16 rows/warp), k-tile 64, double-
// buffered; 2 decoupled CTAs/SM. tf32-bit operands, paired conflict-free
// LDS.64 (AW=72), PV A-frags from QK C-fragments (P never in smem).
// ---------------------------------------------------------------------------
__global__ __launch_bounds__(256, 2)
void attn_tf32(float* __restrict__ ctx)
{
    extern __shared__ uint32_t smu[];
    uint32_t* Qs = smu;                          // 128*AW
    uint32_t* Ks = Qs + 128 * AW;                // [2][64*AW]
    uint32_t* Vs = Ks + 2 * 64 * AW;             // [2][64*AW]  ([d][s_local])
    unsigned* MB = (unsigned*)(Vs + 2 * 64 * AW);// [2][256]

    const int tid = threadIdx.x, lane = tid & 31, w = tid >> 5;
    const int lr = lane >> 2, lc = lane & 3;
    const int bh = blockIdx.z * Hx + blockIdx.x;
    const int qbase = blockIdx.y * 128;
    const uint32_t* Qg = g_Q  + (size_t)bh * Sx * DKx;
    const uint32_t* Kg = g_K  + (size_t)bh * Sx * DKx;
    const uint32_t* Vg = g_Vt + (size_t)bh * Sx * DKx;   // [d][s]
    const unsigned* mbg = g_mb + ((size_t)blockIdx.z * Sx + qbase) * (Sx / 32);

    #pragma unroll
    for (int i = 0; i < 8; i++) {
        int q = tid + i * 256;
        int row = q >> 4, cq = (q & 15) * 4;
        cp16(Qs + row * AW + cq, Qg + (size_t)(qbase + row) * DKx + cq);
    }

    auto load_kv = [&](int st, int kb) {
        #pragma unroll
        for (int i = 0; i < 4; i++) {
            int q = tid + i * 256;
            int row = q >> 4, cq = (q & 15) * 4;
            cp16(Ks + (st * 64 + row) * AW + cq, Kg + (size_t)(kb + row) * DKx + cq);
            cp16(Vs + (st * 64 + row) * AW + cq, Vg + (size_t)row * Sx + kb + cq);
        }
        cp4(MB + st * 256 + tid,
            mbg + (size_t)(tid >> 1) * (Sx / 32) + (kb >> 5) + (tid & 1));
        CP_COMMIT();
    };
    load_kv(0, 0);

    float O[8][4];
    #pragma unroll
    for (int j = 0; j < 8; j++)
        #pragma unroll
        for (int k = 0; k < 4; k++) O[j][k] = 0.f;
    float mrun[2] = {-1e30f, -1e30f};
    float lrun[2] = {0.f, 0.f};

    const int NIT = Sx / 64;
    for (int it = 0; it < NIT; it++) {
        if (it + 1 < NIT) { load_kv((it + 1) & 1, (it + 1) * 64); CP_WAIT(1); }
        else              { CP_WAIT(0); }
        __syncthreads();
        const uint32_t* ks_ = Ks + (it & 1) * 64 * AW;
        const uint32_t* vs_ = Vs + (it & 1) * 64 * AW;
        const unsigned* mb_ = MB + (it & 1) * 256;

        // ---- S = Q K^T (paired LDS.64 fragment loads, no cvt) ----
        float S[8][4];
        #pragma unroll
        for (int j = 0; j < 8; j++)
            #pragma unroll
            for (int k = 0; k < 4; k++) S[j][k] = 0.f;

        #pragma unroll
        for (int ks = 0; ks < 8; ks++) {
            const int kb = ks * 8 + 2 * lc;
            uint32_t qf[4], kf[8][2];
            {
                const uint32_t* p = Qs + (w * 16 + lr) * AW + kb;
                uint2 p0 = *(const uint2*)p;
                uint2 p1 = *(const uint2*)(p + 8 * AW);
                qf[0] = p0.x; qf[1] = p1.x; qf[2] = p0.y; qf[3] = p1.y;
            }
            #pragma unroll
            for (int nt = 0; nt < 8; nt++) {
                uint2 q0 = *(const uint2*)(ks_ + (nt * 8 + lr) * AW + kb);
                kf[nt][0] = q0.x; kf[nt][1] = q0.y;
            }
            #pragma unroll
            for (int nt = 0; nt < 8; nt++)
                mma8(S[nt], qf, kf[nt]);
        }

        // ---- mask + online softmax (p stays in S registers) ----
        {
            const int rl = w * 16 + lr;
            const unsigned m0a = mb_[rl * 2],       m0b = mb_[rl * 2 + 1];
            const unsigned m1a = mb_[(rl + 8) * 2], m1b = mb_[(rl + 8) * 2 + 1];
            #pragma unroll
            for (int nt = 0; nt < 8; nt++) {
                const int sh = (nt * 8 + 2 * lc) & 31;
                const unsigned wa = (nt < 4) ? m0a : m0b;
                const unsigned wb = (nt < 4) ? m1a : m1b;
                S[nt][0] = ((wa >> sh) & 1)       ? S[nt][0] * 0.125f : -1e9f;
                S[nt][1] = ((wa >> (sh + 1)) & 1) ? S[nt][1] * 0.125f : -1e9f;
                S[nt][2] = ((wb >> sh) & 1)       ? S[nt][2] * 0.125f : -1e9f;
                S[nt][3] = ((wb >> (sh + 1)) & 1) ? S[nt][3] * 0.125f : -1e9f;
            }
            #pragma unroll
            for (int hf = 0; hf < 2; hf++) {
                float mx = -1e30f;
                #pragma unroll
                for (int nt = 0; nt < 8; nt++)
                    mx = fmaxf(mx, fmaxf(S[nt][2 * hf], S[nt][2 * hf + 1]));
                mx = fmaxf(mx, __shfl_xor_sync(0xffffffffu, mx, 1));
                mx = fmaxf(mx, __shfl_xor_sync(0xffffffffu, mx, 2));
                const float mnew = fmaxf(mrun[hf], mx);
                const float scl = __expf(mrun[hf] - mnew);
                mrun[hf] = mnew;
                float rs = 0.f;
                #pragma unroll
                for (int nt = 0; nt < 8; nt++) {
                    float p0 = __expf(S[nt][2 * hf]     - mnew);
                    float p1 = __expf(S[nt][2 * hf + 1] - mnew);
                    S[nt][2 * hf] = p0; S[nt][2 * hf + 1] = p1;
                    rs += p0 + p1;
                }
                rs += __shfl_xor_sync(0xffffffffu, rs, 1);
                rs += __shfl_xor_sync(0xffffffffu, rs, 2);
                lrun[hf] = lrun[hf] * scl + rs;
                #pragma unroll
                for (int nd = 0; nd < 8; nd++) {
                    O[nd][2 * hf]     *= scl;
                    O[nd][2 * hf + 1] *= scl;
                }
            }
        }

        // ---- O += P @ V : A-frag from S's C-fragment registers.
        #pragma unroll
        for (int ks = 0; ks < 8; ks++) {
            const int kb = ks * 8 + 2 * lc;
            uint32_t pf[4], vf[8][2];
            pf[0] = f2tf(S[ks][0]);
            pf[1] = f2tf(S[ks][2]);
            pf[2] = f2tf(S[ks][1]);
            pf[3] = f2tf(S[ks][3]);
            #pragma unroll
            for (int nt = 0; nt < 8; nt++) {
                uint2 q0 = *(const uint2*)(vs_ + (nt * 8 + lr) * AW + kb);
                vf[nt][0] = q0.x; vf[nt][1] = q0.y;
            }
            #pragma unroll
            for (int nt = 0; nt < 8; nt++)
                mma8(O[nt], pf, vf[nt]);
        }
        __syncthreads();
    }

    #pragma unroll
    for (int hf = 0; hf < 2; hf++) {
        const float inv = 1.f / lrun[hf];
        const int row = qbase + w * 16 + lr + hf * 8;
        float* dst = ctx + ((size_t)bh * Sx + row) * DKx;
        #pragma unroll
        for (int nd = 0; nd < 8; nd++)
            *(float2*)&dst[nd * 8 + 2 * lc] =
                make_float2(O[nd][2 * hf] * inv, O[nd][2 * hf + 1] * inv);
    }
}

// ---------------------------------------------------------------------------
extern "C" void kernel_launch(void* const* d_in, const int* in_sizes, int n_in,
                              void* d_out, int out_size)
{
    const float* query = (const float*)d_in[0];
    const float* key   = (const float*)d_in[1];
    const float* value = (const float*)d_in[2];
    const int*   mask  = (const int*)d_in[3];
    const float* Wq = (const float*)d_in[4];
    const float* bq = (const float*)d_in[5];
    const float* Wk = (const float*)d_in[6];
    const float* bk = (const float*)d_in[7];
    const float* Wv = (const float*)d_in[8];
    const float* bv = (const float*)d_in[9];
    const float* Wo = (const float*)d_in[10];
    const float* bo = (const float*)d_in[11];
    float* out = (float*)d_out;

    uint32_t *Qb, *Kb, *Vb; float* Cb; unsigned* Mb;
    cudaGetSymbolAddress((void**)&Qb, g_Q);
    cudaGetSymbolAddress((void**)&Kb, g_K);
    cudaGetSymbolAddress((void**)&Vb, g_Vt);
    cudaGetSymbolAddress((void**)&Cb, g_C);
    cudaGetSymbolAddress((void**)&Mb, g_mb);

    const int GSM = 73728;
    const int ASM = (128 + 128 + 128) * AW * 4 + 2048;   // 112640 -> 2 CTAs/SM
    cudaFuncSetAttribute(gemm_qkv,    cudaFuncAttributeMaxDynamicSharedMemorySize, GSM);
    cudaFuncSetAttribute(gemm_one<1>, cudaFuncAttributeMaxDynamicSharedMemorySize, GSM);
    cudaFuncSetAttribute(attn_tf32,   cudaFuncAttributeMaxDynamicSharedMemorySize, ASM);

    dim3 blk(256);
    // Merged QKV projection: 1536 CTAs, tails self-fill via work-stealing.
    gemm_qkv<<<dim3(64, 8, 3), blk, GSM>>>(query, Wq, bq, Qb,
                                           key,   Wk, bk, Kb,
                                           value, Wv, bv, Vb);                 // 1
    pack_mask<<<65536, 256>>>(mask, Mb);                                       // 2
    attn_tf32<<<dim3(Hx, Sx / 128, Bx), blk, ASM>>>(Cb);                       // 3
    gemm_one<1><<<dim3(64, 8), blk, GSM>>>(Cb, Wo, bo, out);                   // 4
}